// round 11
// baseline (speedup 1.0000x reference)
#include <cuda_runtime.h>
#include <cuda_fp16.h>
#include <cstdint>

// TALayer = 9-tap conv, tap offsets d_j = 16*(j/3)+(j%3)-17.
// GEMM: D[o,t] = sum_k W[o,k]*X[k,t], k=(j,c), K=576.
// fp16 m16n8k16. x pre-converted to fp16, t-major, c-words PERMUTED so each
// B-fragment (kg0,kg1) pair is one LDS.64. Triple-buffered cp.async staging.
// 1 CTA/SM x 512 thr, warp tile = 32o x 32t, T_TILE = 256.

#define T_LEN   65536
#define TP      65600        // 32 pad + 65536 + 32 pad
#define NB      8
#define NO      64
#define NC      64
#define T_TILE  256
#define HALO    17
#define XROWS   290
#define XPW     36           // words per smem x row (144B, bank-clean)
#define NCHUNK  36
#define GRID    148
#define NTILES  2048

// smem byte offsets
#define WFOFF   0
#define WFBYTES (NCHUNK*4*32*16)     // 73728
#define XS0     WFBYTES
#define XBUFB   (XROWS*XPW*4)        // 41760
#define SMTOT   (XS0 + 3*XBUFB)      // 199008

__device__ uint32_t g_wfrag[NCHUNK*4*32*4];
// x fp16, [b][t+32][c-words permuted], rows of 128B, pads zeroed.
__device__ __align__(16) __half g_xt[(size_t)NB * TP * NC];

__device__ __forceinline__ uint32_t packh2(float lo, float hi) {
    __half2 h = __floats2half2_rn(lo, hi);
    return *(uint32_t*)&h;
}

// fused: zero pads (first NB*64*32 threads) + W fragment prep
__global__ void prep_misc(const float* __restrict__ w) {
    int tid = blockIdx.x * blockDim.x + threadIdx.x;
    if (tid < NB * 64 * 32) {
        int b = tid / (64*32), r = (tid >> 5) & 63, wd = tid & 31;
        int tp = (r < 32) ? r : (TP - 64 + r);
        ((uint32_t*)g_xt)[((size_t)b*TP + tp)*32 + wd] = 0;
        return;
    }
    int i = tid - NB * 64 * 32;
    if (i >= NCHUNK * 128) return;
    int q = i >> 7, rr = i & 127, mt = rr >> 5, lane = rr & 31;
    int j = q >> 2, cq = q & 3;
    int o0 = mt * 16 + (lane >> 2);
    int c0 = cq * 16 + (lane & 3) * 2;
    uint4 u;
    u.x = packh2(w[o0*576 + c0*9 + j],        w[o0*576 + (c0+1)*9 + j]);
    u.y = packh2(w[(o0+8)*576 + c0*9 + j],    w[(o0+8)*576 + (c0+1)*9 + j]);
    u.z = packh2(w[o0*576 + (c0+8)*9 + j],    w[o0*576 + (c0+9)*9 + j]);
    u.w = packh2(w[(o0+8)*576 + (c0+8)*9 + j],w[(o0+8)*576 + (c0+9)*9 + j]);
    ((uint4*)g_wfrag)[q * 128 + mt * 32 + lane] = u;
}

// Transpose + convert: x[b][c][t] f32 -> g_xt[b][32+t][perm(c-word)] fp16.
__global__ void conv_x(const float* __restrict__ x) {
    __shared__ __half tile[256][66];
    int b  = blockIdx.x >> 8;
    int t0 = (blockIdx.x & 255) << 8;
    int tid = threadIdx.x;
#pragma unroll 8
    for (int c = 0; c < 64; ++c)
        tile[tid][c] = __float2half_rn(x[((size_t)(b*64 + c))*T_LEN + t0 + tid]);
    __syncthreads();
    uint32_t* dst = (uint32_t*)g_xt;
#pragma unroll 8
    for (int it = 0; it < 32; ++it) {
        int idx = it * 256 + tid;
        int i = idx >> 5, wd = idx & 31;
        __half2 h2;
        h2.x = tile[i][2*wd]; h2.y = tile[i][2*wd + 1];
        // permute within 8-word block: pos = (wi&3)*2 + (wi>>2)
        int blk = wd >> 3, wi = wd & 7;
        int pos = blk * 8 + (wi & 3) * 2 + (wi >> 2);
        dst[((size_t)b*TP + 32 + t0 + i)*32 + pos] = *(uint32_t*)&h2;
    }
}

extern __shared__ char sm[];

__device__ __forceinline__ uint32_t s2u(const void* p) {
    uint32_t a;
    asm("{ .reg .u64 t; cvta.to.shared.u64 t, %1; cvt.u32.u64 %0, t; }"
        : "=r"(a) : "l"(p));
    return a;
}

#define CP_ASYNC16(d, s) \
    asm volatile("cp.async.cg.shared.global [%0], [%1], 16;" :: "r"(d), "l"(s))
#define CP_COMMIT() asm volatile("cp.async.commit_group;" ::: "memory")
#define CP_WAIT1()  asm volatile("cp.async.wait_group 1;" ::: "memory")

__device__ __forceinline__ void stage_x(int tile, uint32_t dstu, int tid) {
    const int b  = tile >> 8;
    const int t0 = (tile & 255) << 8;
    const char* src = (const char*)(g_xt + ((size_t)b*TP + 15 + t0) * 64);
#pragma unroll
    for (int s = 0; s < 5; ++s) {
        int idx = s * 512 + tid;
        if (idx < XROWS * 8) {
            int r = idx >> 3, ch = idx & 7;
            CP_ASYNC16(dstu + r*(XPW*4) + ch*16, src + (size_t)r*128 + ch*16);
        }
    }
}

__global__ __launch_bounds__(512, 1) void taconv_mma(
    const float* __restrict__ bias, float* __restrict__ out)
{
    const int tid  = threadIdx.x;
    const int wid  = tid >> 5;
    const int lane = tid & 31;
    const int og   = wid & 1;
    const int tg   = wid >> 1;

    {
        const uint4* gw = (const uint4*)g_wfrag;
        uint4* sw = (uint4*)(sm + WFOFF);
        for (int i = tid; i < NCHUNK * 128; i += 512) sw[i] = gw[i];
    }
    const int oA0 = og * 32 + (lane >> 2);
    float bv[2][2];
#pragma unroll
    for (int m = 0; m < 2; ++m) {
        bv[m][0] = __ldg(bias + oA0 + m * 16);
        bv[m][1] = __ldg(bias + oA0 + m * 16 + 8);
    }

    const uint32_t smb = s2u(sm);
    const int wrow = tg * 32 + (lane >> 2);

    int tile = blockIdx.x;
    stage_x(tile, smb + XS0, tid);
    CP_COMMIT();
    if (tile + GRID < NTILES) stage_x(tile + GRID, smb + XS0 + XBUFB, tid);
    CP_COMMIT();

    int cur = 0;
    for (; tile < NTILES; tile += GRID) {
        CP_WAIT1();
        __syncthreads();

        // prefetch tile+2 into the third buffer
        int nxt = cur + 2; if (nxt >= 3) nxt -= 3;
        if (tile + 2 * GRID < NTILES)
            stage_x(tile + 2 * GRID, smb + XS0 + nxt * XBUFB, tid);
        CP_COMMIT();

        const uint32_t* xs = (const uint32_t*)(sm + XS0 + cur * XBUFB);
        const uint4* wf_base = (const uint4*)(sm + WFOFF);

        float acc[2][4][4];
#pragma unroll
        for (int m = 0; m < 2; ++m)
#pragma unroll
            for (int n = 0; n < 4; ++n)
#pragma unroll
                for (int r = 0; r < 4; ++r) acc[m][n][r] = 0.0f;

#pragma unroll
        for (int j = 0; j < 9; ++j) {
            const int offj = 16 * (j / 3) + (j % 3);
#pragma unroll
            for (int cq = 0; cq < 4; ++cq) {
                const int q = j * 4 + cq;
                uint4 wf[2];
#pragma unroll
                for (int m = 0; m < 2; ++m)
                    wf[m] = wf_base[(q * 4 + og * 2 + m) * 32 + lane];

                uint2 bb[4];
                const uint2* bp = (const uint2*)
                    (xs + (wrow + offj) * XPW + cq * 8 + 2 * (lane & 3));
#pragma unroll
                for (int nt = 0; nt < 4; ++nt)
                    bb[nt] = bp[nt * 4 * XPW];
#pragma unroll
                for (int m = 0; m < 2; ++m)
#pragma unroll
                    for (int nt = 0; nt < 4; ++nt)
                        asm volatile(
                            "mma.sync.aligned.m16n8k16.row.col.f32.f16.f16.f32 "
                            "{%0,%1,%2,%3}, {%4,%5,%6,%7}, {%8,%9}, {%0,%1,%2,%3};"
                            : "+f"(acc[m][nt][0]), "+f"(acc[m][nt][1]),
                              "+f"(acc[m][nt][2]), "+f"(acc[m][nt][3])
                            : "r"(wf[m].x), "r"(wf[m].y),
                              "r"(wf[m].z), "r"(wf[m].w),
                              "r"(bb[nt].x), "r"(bb[nt].y));
            }
        }

        const int b  = tile >> 8;
        const int t0 = (tile & 255) << 8;
        float* ob = out + (size_t)b * NO * T_LEN + t0 + tg * 32 + 2 * (lane & 3);
#pragma unroll
        for (int m = 0; m < 2; ++m) {
            int oA = oA0 + m * 16;
#pragma unroll
            for (int nt = 0; nt < 4; ++nt) {
                float2 v0 = make_float2(acc[m][nt][0] + bv[m][0],
                                        acc[m][nt][1] + bv[m][0]);
                float2 v1 = make_float2(acc[m][nt][2] + bv[m][1],
                                        acc[m][nt][3] + bv[m][1]);
                *(float2*)(ob + (size_t)oA * T_LEN + nt * 8) = v0;
                *(float2*)(ob + (size_t)(oA + 8) * T_LEN + nt * 8) = v1;
            }
        }
        cur = cur + 1; if (cur >= 3) cur = 0;
    }
}

extern "C" void kernel_launch(void* const* d_in, const int* in_sizes, int n_in,
                              void* d_out, int out_size) {
    const float* x    = (const float*)d_in[0];
    const float* w    = (const float*)d_in[1];
    const float* bias = (const float*)d_in[2];
    float* out = (float*)d_out;

    prep_misc<<<(NB*64*32 + NCHUNK*128 + 255) / 256, 256>>>(w);
    conv_x<<<NB * 256, 256>>>(x);

    cudaFuncSetAttribute(taconv_mma,
                         cudaFuncAttributeMaxDynamicSharedMemorySize, SMTOT);
    taconv_mma<<<GRID, 512, SMTOT>>>(bias, out);
}

// round 12
// speedup vs baseline: 1.0466x; 1.0466x over previous
#include <cuda_runtime.h>
#include <cuda_fp16.h>
#include <cstdint>

// TALayer = 9-tap conv, tap offsets d_j = 16*(j/3)+(j%3)-17.
// GEMM: D[o,t] = sum_k W[o,k]*X[k,t], k=(j,c), K=576.
// fp16 m16n8k16. x pre-converted fp16, t-major, c-words permuted so each
// B-fragment (kg0,kg1) is one LDS.64. Row stride 160B (8 mod 32 words)
// => conflict-free 64-bit LDS. Triple-buffered cp.async staging.
// 1 CTA/SM x 512 thr, warp tile = 32o x 32t, T_TILE = 256.

#define T_LEN   65536
#define TP      65600        // 32 pad + 65536 + 32 pad
#define NB      8
#define NO      64
#define NC      64
#define T_TILE  256
#define HALO    17
#define XROWS   290
#define XPW     40           // words per smem x row (160B; 8 mod 32 -> bank-clean LDS.64)
#define NCHUNK  36
#define GRID    148
#define NTILES  2048

// smem byte offsets
#define WFOFF   0
#define WFBYTES (NCHUNK*4*32*16)     // 73728
#define XS0     WFBYTES
#define XBUFB   (XROWS*XPW*4)        // 46400
#define SMTOT   (XS0 + 3*XBUFB)      // 212928

__device__ uint32_t g_wfrag[NCHUNK*4*32*4];
// x fp16, [b][t+32][c-words permuted], rows of 128B, pads zeroed.
__device__ __align__(16) __half g_xt[(size_t)NB * TP * NC];

__device__ __forceinline__ uint32_t packh2(float lo, float hi) {
    __half2 h = __floats2half2_rn(lo, hi);
    return *(uint32_t*)&h;
}

__global__ void prep_w(const float* __restrict__ w) {
    int i = blockIdx.x * blockDim.x + threadIdx.x;
    if (i >= NCHUNK * 128) return;
    int q = i >> 7, rr = i & 127, mt = rr >> 5, lane = rr & 31;
    int j = q >> 2, cq = q & 3;
    int o0 = mt * 16 + (lane >> 2);
    int c0 = cq * 16 + (lane & 3) * 2;
    uint4 u;
    u.x = packh2(w[o0*576 + c0*9 + j],        w[o0*576 + (c0+1)*9 + j]);
    u.y = packh2(w[(o0+8)*576 + c0*9 + j],    w[(o0+8)*576 + (c0+1)*9 + j]);
    u.z = packh2(w[o0*576 + (c0+8)*9 + j],    w[o0*576 + (c0+9)*9 + j]);
    u.w = packh2(w[(o0+8)*576 + (c0+8)*9 + j],w[(o0+8)*576 + (c0+9)*9 + j]);
    ((uint4*)g_wfrag)[q * 128 + mt * 32 + lane] = u;
}

// Transpose + convert: x[b][c][t] f32 -> g_xt[b][32+t][perm(c-word)] fp16.
// Blocks covering the batch edges also zero the 32-row pads (disjoint writes).
__global__ void conv_x(const float* __restrict__ x) {
    __shared__ __half tile[256][66];
    int b  = blockIdx.x >> 8;
    int tt = blockIdx.x & 255;
    int t0 = tt << 8;
    int tid = threadIdx.x;
    uint32_t* dst = (uint32_t*)g_xt;

    if (tt == 0) {          // zero front pad rows [0,32)
        for (int i = tid; i < 32 * 32; i += 256)
            dst[((size_t)b*TP + (i >> 5))*32 + (i & 31)] = 0;
    } else if (tt == 255) { // zero back pad rows [TP-32, TP)
        for (int i = tid; i < 32 * 32; i += 256)
            dst[((size_t)b*TP + TP - 32 + (i >> 5))*32 + (i & 31)] = 0;
    }

#pragma unroll 8
    for (int c = 0; c < 64; ++c)
        tile[tid][c] = __float2half_rn(x[((size_t)(b*64 + c))*T_LEN + t0 + tid]);
    __syncthreads();
#pragma unroll 8
    for (int it = 0; it < 32; ++it) {
        int idx = it * 256 + tid;
        int i = idx >> 5, wd = idx & 31;
        __half2 h2;
        h2.x = tile[i][2*wd]; h2.y = tile[i][2*wd + 1];
        // permute within 8-word block: pos = (wi&3)*2 + (wi>>2)
        int blk = wd >> 3, wi = wd & 7;
        int pos = blk * 8 + (wi & 3) * 2 + (wi >> 2);
        dst[((size_t)b*TP + 32 + t0 + i)*32 + pos] = *(uint32_t*)&h2;
    }
}

extern __shared__ char sm[];

__device__ __forceinline__ uint32_t s2u(const void* p) {
    uint32_t a;
    asm("{ .reg .u64 t; cvta.to.shared.u64 t, %1; cvt.u32.u64 %0, t; }"
        : "=r"(a) : "l"(p));
    return a;
}

#define CP_ASYNC16(d, s) \
    asm volatile("cp.async.cg.shared.global [%0], [%1], 16;" :: "r"(d), "l"(s))
#define CP_COMMIT() asm volatile("cp.async.commit_group;" ::: "memory")
#define CP_WAIT1()  asm volatile("cp.async.wait_group 1;" ::: "memory")

__device__ __forceinline__ void stage_x(int tile, uint32_t dstu, int tid) {
    const int b  = tile >> 8;
    const int t0 = (tile & 255) << 8;
    const char* src = (const char*)(g_xt + ((size_t)b*TP + 15 + t0) * 64);
#pragma unroll
    for (int s = 0; s < 5; ++s) {
        int idx = s * 512 + tid;
        if (idx < XROWS * 8) {
            int r = idx >> 3, ch = idx & 7;
            CP_ASYNC16(dstu + r*(XPW*4) + ch*16, src + (size_t)r*128 + ch*16);
        }
    }
}

__global__ __launch_bounds__(512, 1) void taconv_mma(
    const float* __restrict__ bias, float* __restrict__ out)
{
    const int tid  = threadIdx.x;
    const int wid  = tid >> 5;
    const int lane = tid & 31;
    const int og   = wid & 1;
    const int tg   = wid >> 1;

    {
        const uint4* gw = (const uint4*)g_wfrag;
        uint4* sw = (uint4*)(sm + WFOFF);
        for (int i = tid; i < NCHUNK * 128; i += 512) sw[i] = gw[i];
    }
    const int oA0 = og * 32 + (lane >> 2);
    float bv[2][2];
#pragma unroll
    for (int m = 0; m < 2; ++m) {
        bv[m][0] = __ldg(bias + oA0 + m * 16);
        bv[m][1] = __ldg(bias + oA0 + m * 16 + 8);
    }

    const uint32_t smb = s2u(sm);
    const int wrow = tg * 32 + (lane >> 2);

    int tile = blockIdx.x;
    stage_x(tile, smb + XS0, tid);
    CP_COMMIT();
    if (tile + GRID < NTILES) stage_x(tile + GRID, smb + XS0 + XBUFB, tid);
    CP_COMMIT();

    int cur = 0;
    for (; tile < NTILES; tile += GRID) {
        CP_WAIT1();
        __syncthreads();

        // prefetch tile+2 into the third buffer
        int nxt = cur + 2; if (nxt >= 3) nxt -= 3;
        if (tile + 2 * GRID < NTILES)
            stage_x(tile + 2 * GRID, smb + XS0 + nxt * XBUFB, tid);
        CP_COMMIT();

        const uint32_t* xs = (const uint32_t*)(sm + XS0 + cur * XBUFB);
        const uint4* wf_base = (const uint4*)(sm + WFOFF);

        float acc[2][4][4];
#pragma unroll
        for (int m = 0; m < 2; ++m)
#pragma unroll
            for (int n = 0; n < 4; ++n)
#pragma unroll
                for (int r = 0; r < 4; ++r) acc[m][n][r] = 0.0f;

#pragma unroll
        for (int j = 0; j < 9; ++j) {
            const int offj = 16 * (j / 3) + (j % 3);
#pragma unroll
            for (int cq = 0; cq < 4; ++cq) {
                const int q = j * 4 + cq;
                uint4 wf[2];
#pragma unroll
                for (int m = 0; m < 2; ++m)
                    wf[m] = wf_base[(q * 4 + og * 2 + m) * 32 + lane];

                uint2 bb[4];
                const uint2* bp = (const uint2*)
                    (xs + (wrow + offj) * XPW + cq * 8 + 2 * (lane & 3));
#pragma unroll
                for (int nt = 0; nt < 4; ++nt)
                    bb[nt] = bp[nt * 4 * XPW];
#pragma unroll
                for (int m = 0; m < 2; ++m)
#pragma unroll
                    for (int nt = 0; nt < 4; ++nt)
                        asm volatile(
                            "mma.sync.aligned.m16n8k16.row.col.f32.f16.f16.f32 "
                            "{%0,%1,%2,%3}, {%4,%5,%6,%7}, {%8,%9}, {%0,%1,%2,%3};"
                            : "+f"(acc[m][nt][0]), "+f"(acc[m][nt][1]),
                              "+f"(acc[m][nt][2]), "+f"(acc[m][nt][3])
                            : "r"(wf[m].x), "r"(wf[m].y),
                              "r"(wf[m].z), "r"(wf[m].w),
                              "r"(bb[nt].x), "r"(bb[nt].y));
            }
        }

        const int b  = tile >> 8;
        const int t0 = (tile & 255) << 8;
        float* ob = out + (size_t)b * NO * T_LEN + t0 + tg * 32 + 2 * (lane & 3);
#pragma unroll
        for (int m = 0; m < 2; ++m) {
            int oA = oA0 + m * 16;
#pragma unroll
            for (int nt = 0; nt < 4; ++nt) {
                float2 v0 = make_float2(acc[m][nt][0] + bv[m][0],
                                        acc[m][nt][1] + bv[m][0]);
                float2 v1 = make_float2(acc[m][nt][2] + bv[m][1],
                                        acc[m][nt][3] + bv[m][1]);
                *(float2*)(ob + (size_t)oA * T_LEN + nt * 8) = v0;
                *(float2*)(ob + (size_t)(oA + 8) * T_LEN + nt * 8) = v1;
            }
        }
        cur = cur + 1; if (cur >= 3) cur = 0;
    }
}

extern "C" void kernel_launch(void* const* d_in, const int* in_sizes, int n_in,
                              void* d_out, int out_size) {
    const float* x    = (const float*)d_in[0];
    const float* w    = (const float*)d_in[1];
    const float* bias = (const float*)d_in[2];
    float* out = (float*)d_out;

    prep_w<<<(NCHUNK * 128 + 255) / 256, 256>>>(w);
    conv_x<<<NB * 256, 256>>>(x);

    cudaFuncSetAttribute(taconv_mma,
                         cudaFuncAttributeMaxDynamicSharedMemorySize, SMTOT);
    taconv_mma<<<GRID, 512, SMTOT>>>(bias, out);
}